// round 2
// baseline (speedup 1.0000x reference)
#include <cuda_runtime.h>
#include <math.h>

#define B 64
#define C 256

typedef unsigned long long u64;

// ---------------- f32x2 packed-math helpers ----------------
__device__ __forceinline__ u64 pack2(float lo, float hi){
    u64 r; asm("mov.b64 %0, {%1, %2};" : "=l"(r) : "f"(lo), "f"(hi)); return r;
}
__device__ __forceinline__ u64 dup2(float v){
    u64 r; asm("mov.b64 %0, {%1, %1};" : "=l"(r) : "f"(v)); return r;
}
__device__ __forceinline__ void fma2(u64 &d, u64 a, u64 b){
    asm("fma.rn.f32x2 %0, %1, %2, %0;" : "+l"(d) : "l"(a), "l"(b));
}
__device__ __forceinline__ u64 add2(u64 a, u64 b){
    u64 d; asm("add.rn.f32x2 %0, %1, %2;" : "=l"(d) : "l"(a), "l"(b)); return d;
}
__device__ __forceinline__ float2 unpk(u64 v){
    float2 f; asm("mov.b64 {%0, %1}, %2;" : "=f"(f.x), "=f"(f.y) : "l"(v)); return f;
}

// ---------------- scratch ----------------
__device__ float g_lf[B*C*7*7];
__device__ float g_mf[B*C*5*5];
__device__ float g_sf[B*C*3*3];
__device__ float g_s [B*C*29*29];
__device__ float g_lc[B*C*27*27];
__device__ float g_mc[B*C*25*25];
__device__ float g_sc[B*C*27*27];
__device__ float g_scale_t[C], g_bias_t[C];
__device__ float g_scale_s[C], g_bias_s[C];
__device__ float g_scale_1[C], g_bias_1[C];

// ---------------- BN folding ----------------
__global__ void prep_kernel(const float* bt,const float* gt,const float* bet,const float* mt,const float* vt,
                            const float* bs,const float* gs,const float* bes,const float* ms,const float* vs,
                            const float* b1,const float* g1,const float* be1,const float* m1,const float* v1){
    int c = threadIdx.x;
    { float inv = gt[c]*rsqrtf(vt[c]+1e-5f); g_scale_t[c]=inv; g_bias_t[c]=bt[c]*inv + bet[c] - mt[c]*inv; }
    { float inv = gs[c]*rsqrtf(vs[c]+1e-5f); g_scale_s[c]=inv; g_bias_s[c]=bs[c]*inv + bes[c] - ms[c]*inv; }
    { float inv = g1[c]*rsqrtf(v1[c]+1e-5f); g_scale_1[c]=inv; g_bias_1[c]=b1[c]*inv + be1[c] - m1[c]*inv; }
}

// ---------------- merged template conv 3x3 + BN + ReLU, f32x2 ----------------
// 512 thr = 32 oc-pairs x 16 row-slots. slots: 0-6 large rows, 7-11 medium, 12-14 small.
template<int W, int NP>
__device__ __forceinline__ void row3(const float* ip, const u64* wdA, const u64* wdB,
                                     u64* aA, u64* aB){
#pragma unroll
    for (int kh = 0; kh < 3; kh++){
        float rv[2*NP+2];
#pragma unroll
        for (int j = 0; j < 2*NP+2; j++) rv[j] = ip[kh*W + j];
        u64 pe[NP+1], po[NP];
#pragma unroll
        for (int p = 0; p <= NP; p++) pe[p] = pack2(rv[2*p], rv[2*p+1]);
#pragma unroll
        for (int p = 0; p < NP; p++) po[p] = pack2(rv[2*p+1], rv[2*p+2]);
#pragma unroll
        for (int p = 0; p < NP; p++){
            fma2(aA[p], pe[p],   wdA[kh*3+0]);
            fma2(aA[p], po[p],   wdA[kh*3+1]);
            fma2(aA[p], pe[p+1], wdA[kh*3+2]);
            fma2(aB[p], pe[p],   wdB[kh*3+0]);
            fma2(aB[p], po[p],   wdB[kh*3+1]);
            fma2(aB[p], pe[p+1], wdB[kh*3+2]);
        }
    }
}

template<int OH, int NP>
__device__ __forceinline__ void tmpl_store(float* out, int b, int oc0, int row,
                                           const u64* aA, const u64* aB){
    float scA = g_scale_t[oc0],   biA = g_bias_t[oc0];
    float scB = g_scale_t[oc0+1], biB = g_bias_t[oc0+1];
    float* pA = out + (((size_t)b*C + oc0  )*OH + row)*OH;
    float* pB = out + (((size_t)b*C + oc0+1)*OH + row)*OH;
#pragma unroll
    for (int p = 0; p < NP; p++){
        float2 fa = unpk(aA[p]), fb = unpk(aB[p]);
        int col = 2*p;
        if (col < OH){
            float va = fmaf(scA, fa.x, biA); pA[col] = va > 0.f ? va : 0.f;
            float vb = fmaf(scB, fb.x, biB); pB[col] = vb > 0.f ? vb : 0.f;
        }
        if (col+1 < OH){
            float va = fmaf(scA, fa.y, biA); pA[col+1] = va > 0.f ? va : 0.f;
            float vb = fmaf(scB, fb.y, biB); pB[col+1] = vb > 0.f ? vb : 0.f;
        }
    }
}

__global__ void __launch_bounds__(512) tmpl_all(const float* __restrict__ lin,
                                                const float* __restrict__ min_,
                                                const float* __restrict__ sin_,
                                                const float* __restrict__ w,
                                                float* lo, float* mo, float* so){
    __shared__ __align__(16) float s_in[16*155 + 4];
    __shared__ __align__(16) float s_w[144*66];
    int tid = threadIdx.x;
    int ocp = tid & 31, slot = tid >> 5;
    int b = blockIdx.x, ocbase = blockIdx.y * 64;
    int oc0 = ocbase + ocp*2;

    u64 aA[4] = {0,0,0,0}, aB[4] = {0,0,0,0};

    for (int ic0 = 0; ic0 < C; ic0 += 16){
        __syncthreads();
#pragma unroll 1
        for (int idx = tid; idx < 16*155; idx += 512){
            int ic = idx / 155, r = idx % 155;
            size_t cb = (size_t)b*C + ic0 + ic;
            float v;
            if (r < 81)       v = lin [cb*81 + r];
            else if (r < 130) v = min_[cb*49 + (r-81)];
            else              v = sin_[cb*25 + (r-130)];
            s_in[ic*155 + r] = v;
        }
#pragma unroll 1
        for (int idx = tid; idx < 64*144; idx += 512){
            int oc = idx / 144, r = idx % 144;
            s_w[r*66 + oc] = w[(size_t)(ocbase+oc)*2304 + (size_t)ic0*9 + r];
        }
        __syncthreads();

        if (slot < 7){
            int row = slot;
#pragma unroll 1
            for (int ic = 0; ic < 16; ic++){
                u64 wdA[9], wdB[9];
#pragma unroll
                for (int k = 0; k < 9; k++){
                    u64 pr = *(const u64*)&s_w[(ic*9+k)*66 + ocp*2];
                    float2 f = unpk(pr);
                    wdA[k] = dup2(f.x); wdB[k] = dup2(f.y);
                }
                row3<9,4>(s_in + ic*155 + row*9, wdA, wdB, aA, aB);
            }
        } else if (slot < 12){
            int row = slot - 7;
#pragma unroll 1
            for (int ic = 0; ic < 16; ic++){
                u64 wdA[9], wdB[9];
#pragma unroll
                for (int k = 0; k < 9; k++){
                    u64 pr = *(const u64*)&s_w[(ic*9+k)*66 + ocp*2];
                    float2 f = unpk(pr);
                    wdA[k] = dup2(f.x); wdB[k] = dup2(f.y);
                }
                row3<7,3>(s_in + ic*155 + 81 + row*7, wdA, wdB, aA, aB);
            }
        } else if (slot < 15){
            int row = slot - 12;
#pragma unroll 1
            for (int ic = 0; ic < 16; ic++){
                u64 wdA[9], wdB[9];
#pragma unroll
                for (int k = 0; k < 9; k++){
                    u64 pr = *(const u64*)&s_w[(ic*9+k)*66 + ocp*2];
                    float2 f = unpk(pr);
                    wdA[k] = dup2(f.x); wdB[k] = dup2(f.y);
                }
                row3<5,2>(s_in + ic*155 + 130 + row*5, wdA, wdB, aA, aB);
            }
        }
    }

    if (slot < 7)       tmpl_store<7,4>(lo, b, oc0, slot,      aA, aB);
    else if (slot < 12) tmpl_store<5,3>(mo, b, oc0, slot - 7,  aA, aB);
    else if (slot < 15) tmpl_store<3,2>(so, b, oc0, slot - 12, aA, aB);
}

// ---------------- search conv 3x3 + BN + ReLU (31->29), f32x2 ----------------
__global__ void __launch_bounds__(256) conv_search(const float* __restrict__ in,
                                                   const float* __restrict__ w){
    __shared__ __align__(16) float s_in[4*18*33 + 4];
    __shared__ float2 s_w2[16*4*9];      // duplicated (w,w) pairs
    int tid = threadIdx.x;
    int c  = tid & 3;
    int r  = (tid >> 2) & 15;
    int cz = tid >> 6;
    int b = blockIdx.x;
    int ocbase = blockIdx.y * 16;
    int row0 = blockIdx.z * 16;

    u64 acc[4][4];
#pragma unroll
    for (int i = 0; i < 4; i++)
#pragma unroll
        for (int p = 0; p < 4; p++) acc[i][p] = 0ull;

    const float* inb = in + (size_t)b * C * 31 * 31;
    for (int ic0 = 0; ic0 < C; ic0 += 4){
        __syncthreads();
#pragma unroll 1
        for (int idx = tid; idx < 4*18*32; idx += 256){
            int col = idx & 31;
            int row = (idx >> 5) % 18;
            int ic  = idx / (18*32);
            int grow = row0 + row;
            float v = 0.f;
            if (col < 31 && grow < 31) v = inb[((ic0+ic)*31 + grow)*31 + col];
            s_in[ic*(18*33) + row*33 + col] = v;
        }
#pragma unroll 1
        for (int idx = tid; idx < 16*4*9; idx += 256){
            int k  = idx % 9;
            int ic = (idx / 9) & 3;
            int oc = idx / 36;
            float v = w[((size_t)(ocbase+oc)*C + ic0 + ic)*9 + k];
            s_w2[idx] = make_float2(v, v);
        }
        __syncthreads();
#pragma unroll 1
        for (int ic = 0; ic < 4; ic++){
            const float* sp = s_in + ic*(18*33) + r*33 + c*8;
#pragma unroll
            for (int kh = 0; kh < 3; kh++){
                float rv[10];
#pragma unroll
                for (int j = 0; j < 10; j++) rv[j] = sp[kh*33 + j];
                u64 pe[5], po[4];
#pragma unroll
                for (int p = 0; p < 5; p++) pe[p] = pack2(rv[2*p], rv[2*p+1]);
#pragma unroll
                for (int p = 0; p < 4; p++) po[p] = pack2(rv[2*p+1], rv[2*p+2]);
#pragma unroll
                for (int i = 0; i < 4; i++){
                    const u64* wp = (const u64*)&s_w2[((cz*4+i)*4 + ic)*9 + kh*3];
                    u64 w0 = wp[0], w1 = wp[1], w2 = wp[2];
#pragma unroll
                    for (int p = 0; p < 4; p++){
                        fma2(acc[i][p], pe[p],   w0);
                        fma2(acc[i][p], po[p],   w1);
                        fma2(acc[i][p], pe[p+1], w2);
                    }
                }
            }
        }
    }
    int orow = row0 + r;
    if (orow < 29){
#pragma unroll
        for (int i = 0; i < 4; i++){
            int oc = ocbase + cz*4 + i;
            float sc = g_scale_s[oc], bi = g_bias_s[oc];
            float* op = g_s + (((size_t)b*C + oc)*29 + orow)*29;
#pragma unroll
            for (int p = 0; p < 4; p++){
                float2 f = unpk(acc[i][p]);
                int col = c*8 + 2*p;
                if (col < 29){ float v = fmaf(sc, f.x, bi); op[col]   = v > 0.f ? v : 0.f; }
                if (col+1 < 29){ float v = fmaf(sc, f.y, bi); op[col+1] = v > 0.f ? v : 0.f; }
            }
        }
    }
}

// ---------------- per-sample depthwise cross-correlation ----------------
template<int TS, int PAD, int OS>
__global__ void __launch_bounds__(256) corr_kernel(const float* __restrict__ t,
                                                   float* __restrict__ out){
    __shared__ float s_s[4 * 841];
    __shared__ float s_t[4 * TS * TS];
    int tid = threadIdx.x;
    int cl = tid >> 6;
    int ps = tid & 63;
    int b = blockIdx.x;
    int c0 = blockIdx.y * 4;

    const float* sb = g_s + ((size_t)b*C + c0) * 841;
#pragma unroll 1
    for (int idx = tid; idx < 4*841; idx += 256) s_s[idx] = sb[idx];
    const float* tb = t + ((size_t)b*C + c0) * TS * TS;
#pragma unroll 1
    for (int idx = tid; idx < 4*TS*TS; idx += 256) s_t[idx] = tb[idx];
    __syncthreads();

    const float* scn = s_s + cl * 841;
    const float* tcn = s_t + cl * TS * TS;
    for (int p = ps; p < OS*OS; p += 64){
        int py = p / OS, px = p % OS;
        float acc = 0.f;
#pragma unroll
        for (int i = 0; i < TS; i++){
            int sy = py + i - PAD;
            if ((unsigned)sy < 29u){
#pragma unroll
                for (int j = 0; j < TS; j++){
                    int sx = px + j - PAD;
                    if ((unsigned)sx < 29u)
                        acc += tcn[i*TS + j] * scn[sy*29 + sx];
                }
            }
        }
        out[(((size_t)b*C + c0 + cl)*OS + py)*OS + px] = acc;
    }
}

// ---------------- fused head, f32x2, 64-px tiles ----------------
__global__ void __launch_bounds__(256) head_kernel(const float* __restrict__ x, int HW,
                                                   const float* __restrict__ w1,
                                                   const float* __restrict__ w2,
                                                   const float* __restrict__ b2,
                                                   float* __restrict__ out){
    __shared__ float s_wm[32*257];
    __shared__ __align__(16) float s_x[32*64];
    __shared__ float s_red[8][64];
    int tid = threadIdx.x;                  // n = layer-1 out channel
    int b = blockIdx.y;
    int p0 = blockIdx.x * 64;
    const float* xb = x + (size_t)b * C * HW;

    u64 acc[32];
#pragma unroll
    for (int p = 0; p < 32; p++) acc[p] = 0ull;

    for (int k0 = 0; k0 < C; k0 += 32){
        __syncthreads();
#pragma unroll 1
        for (int idx = tid; idx < 8192; idx += 256){
            int kk = idx & 31, n = idx >> 5;
            s_wm[kk*257 + n] = w1[n*C + k0 + kk];
        }
#pragma unroll 1
        for (int idx = tid; idx < 2048; idx += 256){
            int p = idx & 63, kk = idx >> 6;
            int gp = p0 + p;
            s_x[kk*64 + p] = (gp < HW) ? xb[(k0+kk)*HW + gp] : 0.f;
        }
        __syncthreads();
#pragma unroll 2
        for (int kk = 0; kk < 32; kk++){
            u64 wd = dup2(s_wm[kk*257 + tid]);
            const u64* xp = (const u64*)(s_x + kk*64);
#pragma unroll
            for (int p = 0; p < 32; p++) fma2(acc[p], xp[p], wd);
        }
    }

    float sc = g_scale_1[tid], bi = g_bias_1[tid], w2v = w2[tid];
#pragma unroll
    for (int p = 0; p < 32; p++){
        float2 f = unpk(acc[p]);
        f.x = fmaxf(fmaf(sc, f.x, bi), 0.f) * w2v;
        f.y = fmaxf(fmaf(sc, f.y, bi), 0.f) * w2v;
        acc[p] = pack2(f.x, f.y);
    }
    int lane = tid & 31, wrp = tid >> 5;
#pragma unroll 1
    for (int p = 0; p < 32; p++){
        u64 v = acc[p];
        v = add2(v, __shfl_xor_sync(0xffffffffu, v, 16));
        v = add2(v, __shfl_xor_sync(0xffffffffu, v, 8));
        v = add2(v, __shfl_xor_sync(0xffffffffu, v, 4));
        v = add2(v, __shfl_xor_sync(0xffffffffu, v, 2));
        v = add2(v, __shfl_xor_sync(0xffffffffu, v, 1));
        if (lane == 0){ float2 f = unpk(v); s_red[wrp][2*p] = f.x; s_red[wrp][2*p+1] = f.y; }
    }
    __syncthreads();
    if (tid < 64){
        float v = 0.f;
#pragma unroll
        for (int wg = 0; wg < 8; wg++) v += s_red[wg][tid];
        int gp = p0 + tid;
        if (gp < HW)
            out[(size_t)b*HW + gp] = 1.f / (1.f + expf(-(v + b2[0])));
    }
}

// ---------------- launch ----------------
extern "C" void kernel_launch(void* const* d_in, const int* in_sizes, int n_in,
                              void* d_out, int out_size){
    const float* large  = (const float*)d_in[0];
    const float* medium = (const float*)d_in[1];
    const float* small  = (const float*)d_in[2];
    const float* search = (const float*)d_in[3];
    const float* wt  = (const float*)d_in[4];
    const float* bt  = (const float*)d_in[5];
    const float* gt  = (const float*)d_in[6];
    const float* bet = (const float*)d_in[7];
    const float* mt  = (const float*)d_in[8];
    const float* vt  = (const float*)d_in[9];
    const float* ws  = (const float*)d_in[10];
    const float* bs  = (const float*)d_in[11];
    const float* gs  = (const float*)d_in[12];
    const float* bes = (const float*)d_in[13];
    const float* ms  = (const float*)d_in[14];
    const float* vs  = (const float*)d_in[15];
    const float* w1  = (const float*)d_in[16];
    const float* b1  = (const float*)d_in[17];
    const float* g1  = (const float*)d_in[18];
    const float* be1 = (const float*)d_in[19];
    const float* m1  = (const float*)d_in[20];
    const float* v1  = (const float*)d_in[21];
    const float* w2  = (const float*)d_in[22];
    const float* b2  = (const float*)d_in[23];
    float* out = (float*)d_out;

    float *lf, *mf, *sf, *lc, *mc, *sc;
    cudaGetSymbolAddress((void**)&lf, g_lf);
    cudaGetSymbolAddress((void**)&mf, g_mf);
    cudaGetSymbolAddress((void**)&sf, g_sf);
    cudaGetSymbolAddress((void**)&lc, g_lc);
    cudaGetSymbolAddress((void**)&mc, g_mc);
    cudaGetSymbolAddress((void**)&sc, g_sc);

    prep_kernel<<<1, 256>>>(bt, gt, bet, mt, vt, bs, gs, bes, ms, vs, b1, g1, be1, m1, v1);

    tmpl_all<<<dim3(64, 4), 512>>>(large, medium, small, wt, lf, mf, sf);
    conv_search<<<dim3(64, 16, 2), 256>>>(search, ws);

    corr_kernel<7, 2, 27><<<dim3(64, 64), 256>>>(lf, lc);
    corr_kernel<5, 0, 25><<<dim3(64, 64), 256>>>(mf, mc);
    corr_kernel<3, 0, 27><<<dim3(64, 64), 256>>>(sf, sc);

    head_kernel<<<dim3(12, 64), 256>>>(lc, 729, w1, w2, b2, out);
    head_kernel<<<dim3(10, 64), 256>>>(mc, 625, w1, w2, b2, out + 64*729);
    head_kernel<<<dim3(12, 64), 256>>>(sc, 729, w1, w2, b2, out + 64*729 + 64*625);
}

// round 3
// speedup vs baseline: 1.0746x; 1.0746x over previous
#include <cuda_runtime.h>
#include <math.h>

#define B 64
#define C 256

typedef unsigned long long u64;

// ---------------- f32x2 packed-math helpers ----------------
__device__ __forceinline__ u64 pack2(float lo, float hi){
    u64 r; asm("mov.b64 %0, {%1, %2};" : "=l"(r) : "f"(lo), "f"(hi)); return r;
}
__device__ __forceinline__ u64 dup2(float v){
    u64 r; asm("mov.b64 %0, {%1, %1};" : "=l"(r) : "f"(v)); return r;
}
__device__ __forceinline__ void fma2(u64 &d, u64 a, u64 b){
    asm("fma.rn.f32x2 %0, %1, %2, %0;" : "+l"(d) : "l"(a), "l"(b));
}
__device__ __forceinline__ u64 add2(u64 a, u64 b){
    u64 d; asm("add.rn.f32x2 %0, %1, %2;" : "=l"(d) : "l"(a), "l"(b)); return d;
}
__device__ __forceinline__ float2 unpk(u64 v){
    float2 f; asm("mov.b64 {%0, %1}, %2;" : "=f"(f.x), "=f"(f.y) : "l"(v)); return f;
}

// ---------------- scratch ----------------
__device__ float g_lf[B*C*7*7];
__device__ float g_mf[B*C*5*5];
__device__ float g_sf[B*C*3*3];
__device__ float g_s [B*C*29*29];
__device__ float g_lc[B*C*27*27];
__device__ float g_mc[B*C*25*25];
__device__ float g_sc[B*C*27*27];
__device__ float g_scale_t[C], g_bias_t[C];
__device__ float g_scale_s[C], g_bias_s[C];
__device__ float g_scale_1[C], g_bias_1[C];

// ---------------- BN folding ----------------
__global__ void prep_kernel(const float* bt,const float* gt,const float* bet,const float* mt,const float* vt,
                            const float* bs,const float* gs,const float* bes,const float* ms,const float* vs,
                            const float* b1,const float* g1,const float* be1,const float* m1,const float* v1){
    int c = threadIdx.x;
    { float inv = gt[c]*rsqrtf(vt[c]+1e-5f); g_scale_t[c]=inv; g_bias_t[c]=bt[c]*inv + bet[c] - mt[c]*inv; }
    { float inv = gs[c]*rsqrtf(vs[c]+1e-5f); g_scale_s[c]=inv; g_bias_s[c]=bs[c]*inv + bes[c] - ms[c]*inv; }
    { float inv = g1[c]*rsqrtf(v1[c]+1e-5f); g_scale_1[c]=inv; g_bias_1[c]=b1[c]*inv + be1[c] - m1[c]*inv; }
}

// ---------------- merged template conv 3x3 + BN + ReLU, f32x2 (kept from R2) -------
template<int W, int NP>
__device__ __forceinline__ void row3(const float* ip, const u64* wdA, const u64* wdB,
                                     u64* aA, u64* aB){
#pragma unroll
    for (int kh = 0; kh < 3; kh++){
        float rv[2*NP+2];
#pragma unroll
        for (int j = 0; j < 2*NP+2; j++) rv[j] = ip[kh*W + j];
        u64 pe[NP+1], po[NP];
#pragma unroll
        for (int p = 0; p <= NP; p++) pe[p] = pack2(rv[2*p], rv[2*p+1]);
#pragma unroll
        for (int p = 0; p < NP; p++) po[p] = pack2(rv[2*p+1], rv[2*p+2]);
#pragma unroll
        for (int p = 0; p < NP; p++){
            fma2(aA[p], pe[p],   wdA[kh*3+0]);
            fma2(aA[p], po[p],   wdA[kh*3+1]);
            fma2(aA[p], pe[p+1], wdA[kh*3+2]);
            fma2(aB[p], pe[p],   wdB[kh*3+0]);
            fma2(aB[p], po[p],   wdB[kh*3+1]);
            fma2(aB[p], pe[p+1], wdB[kh*3+2]);
        }
    }
}

template<int OH, int NP>
__device__ __forceinline__ void tmpl_store(float* out, int b, int oc0, int row,
                                           const u64* aA, const u64* aB){
    float scA = g_scale_t[oc0],   biA = g_bias_t[oc0];
    float scB = g_scale_t[oc0+1], biB = g_bias_t[oc0+1];
    float* pA = out + (((size_t)b*C + oc0  )*OH + row)*OH;
    float* pB = out + (((size_t)b*C + oc0+1)*OH + row)*OH;
#pragma unroll
    for (int p = 0; p < NP; p++){
        float2 fa = unpk(aA[p]), fb = unpk(aB[p]);
        int col = 2*p;
        if (col < OH){
            float va = fmaf(scA, fa.x, biA); pA[col] = va > 0.f ? va : 0.f;
            float vb = fmaf(scB, fb.x, biB); pB[col] = vb > 0.f ? vb : 0.f;
        }
        if (col+1 < OH){
            float va = fmaf(scA, fa.y, biA); pA[col+1] = va > 0.f ? va : 0.f;
            float vb = fmaf(scB, fb.y, biB); pB[col+1] = vb > 0.f ? vb : 0.f;
        }
    }
}

__global__ void __launch_bounds__(512) tmpl_all(const float* __restrict__ lin,
                                                const float* __restrict__ min_,
                                                const float* __restrict__ sin_,
                                                const float* __restrict__ w,
                                                float* lo, float* mo, float* so){
    __shared__ __align__(16) float s_in[16*155 + 4];
    __shared__ __align__(16) float s_w[144*66];
    int tid = threadIdx.x;
    int ocp = tid & 31, slot = tid >> 5;
    int b = blockIdx.x, ocbase = blockIdx.y * 64;
    int oc0 = ocbase + ocp*2;

    u64 aA[4] = {0,0,0,0}, aB[4] = {0,0,0,0};

    for (int ic0 = 0; ic0 < C; ic0 += 16){
        __syncthreads();
#pragma unroll 1
        for (int idx = tid; idx < 16*155; idx += 512){
            int ic = idx / 155, r = idx % 155;
            size_t cb = (size_t)b*C + ic0 + ic;
            float v;
            if (r < 81)       v = lin [cb*81 + r];
            else if (r < 130) v = min_[cb*49 + (r-81)];
            else              v = sin_[cb*25 + (r-130)];
            s_in[ic*155 + r] = v;
        }
#pragma unroll 1
        for (int idx = tid; idx < 64*144; idx += 512){
            int oc = idx / 144, r = idx % 144;
            s_w[r*66 + oc] = w[(size_t)(ocbase+oc)*2304 + (size_t)ic0*9 + r];
        }
        __syncthreads();

        if (slot < 7){
            int row = slot;
#pragma unroll 1
            for (int ic = 0; ic < 16; ic++){
                u64 wdA[9], wdB[9];
#pragma unroll
                for (int k = 0; k < 9; k++){
                    u64 pr = *(const u64*)&s_w[(ic*9+k)*66 + ocp*2];
                    float2 f = unpk(pr);
                    wdA[k] = dup2(f.x); wdB[k] = dup2(f.y);
                }
                row3<9,4>(s_in + ic*155 + row*9, wdA, wdB, aA, aB);
            }
        } else if (slot < 12){
            int row = slot - 7;
#pragma unroll 1
            for (int ic = 0; ic < 16; ic++){
                u64 wdA[9], wdB[9];
#pragma unroll
                for (int k = 0; k < 9; k++){
                    u64 pr = *(const u64*)&s_w[(ic*9+k)*66 + ocp*2];
                    float2 f = unpk(pr);
                    wdA[k] = dup2(f.x); wdB[k] = dup2(f.y);
                }
                row3<7,3>(s_in + ic*155 + 81 + row*7, wdA, wdB, aA, aB);
            }
        } else if (slot < 15){
            int row = slot - 12;
#pragma unroll 1
            for (int ic = 0; ic < 16; ic++){
                u64 wdA[9], wdB[9];
#pragma unroll
                for (int k = 0; k < 9; k++){
                    u64 pr = *(const u64*)&s_w[(ic*9+k)*66 + ocp*2];
                    float2 f = unpk(pr);
                    wdA[k] = dup2(f.x); wdB[k] = dup2(f.y);
                }
                row3<5,2>(s_in + ic*155 + 130 + row*5, wdA, wdB, aA, aB);
            }
        }
    }

    if (slot < 7)       tmpl_store<7,4>(lo, b, oc0, slot,      aA, aB);
    else if (slot < 12) tmpl_store<5,3>(mo, b, oc0, slot - 7,  aA, aB);
    else if (slot < 15) tmpl_store<3,2>(so, b, oc0, slot - 12, aA, aB);
}

// ---------------- search conv v2: 4 oc x 2 rows x 8 cols per thread ----------------
// weights loaded once per (ic,kh) (warp-uniform broadcast), input rows rotated.
__global__ void __launch_bounds__(256) conv_search(const float* __restrict__ in,
                                                   const float* __restrict__ w){
    __shared__ __align__(16) float s_in[4*18*33];        // 4 ic, 18 rows, stride 33
    __shared__ __align__(16) float2 s_w2[32*4*9];        // dup pairs [oc32][ic4][9]
    int tid = threadIdx.x;
    int c  = tid & 3;            // col group (8 cols)
    int rp = (tid >> 2) & 7;     // row pair
    int q  = tid >> 5;           // warp = oc quad (0..7)
    int b = blockIdx.x;
    int ocbase = blockIdx.y * 32;
    int row0 = blockIdx.z * 16;

    u64 acc[4][2][4];
#pragma unroll
    for (int i = 0; i < 4; i++)
#pragma unroll
        for (int r2 = 0; r2 < 2; r2++)
#pragma unroll
            for (int p = 0; p < 4; p++) acc[i][r2][p] = 0ull;

    const float* inb = in + (size_t)b * C * 961;
    for (int ic0 = 0; ic0 < C; ic0 += 4){
        __syncthreads();
#pragma unroll 1
        for (int idx = tid; idx < 4*18*33; idx += 256){
            int ic = idx / 594;
            int rem = idx - ic*594;
            int row = rem / 33, col = rem - row*33;
            int grow = row0 + row;
            float v = 0.f;
            if (col < 31 && grow < 31) v = inb[(ic0+ic)*961 + grow*31 + col];
            s_in[idx] = v;
        }
#pragma unroll 1
        for (int idx = tid; idx < 32*4*9; idx += 256){
            int k  = idx % 9;
            int ic = (idx / 9) & 3;
            int oc = idx / 36;
            float v = w[((size_t)(ocbase+oc)*C + ic0 + ic)*9 + k];
            s_w2[idx] = make_float2(v, v);
        }
        __syncthreads();
#pragma unroll
        for (int ic = 0; ic < 4; ic++){
            const float* sp = s_in + ic*594 + (rp*2)*33 + c*8;
            u64 pea[5], poa[4], peb[5], pob[4];
            {
                float rv[10];
#pragma unroll
                for (int j = 0; j < 10; j++) rv[j] = sp[j];
#pragma unroll
                for (int p = 0; p < 5; p++) pea[p] = pack2(rv[2*p], rv[2*p+1]);
#pragma unroll
                for (int p = 0; p < 4; p++) poa[p] = pack2(rv[2*p+1], rv[2*p+2]);
            }
            {
                float rv[10];
#pragma unroll
                for (int j = 0; j < 10; j++) rv[j] = sp[33 + j];
#pragma unroll
                for (int p = 0; p < 5; p++) peb[p] = pack2(rv[2*p], rv[2*p+1]);
#pragma unroll
                for (int p = 0; p < 4; p++) pob[p] = pack2(rv[2*p+1], rv[2*p+2]);
            }
#pragma unroll
            for (int kh = 0; kh < 3; kh++){
#pragma unroll
                for (int i = 0; i < 4; i++){
                    const u64* wp = (const u64*)&s_w2[((q*4+i)*4 + ic)*9 + kh*3];
                    u64 w0 = wp[0], w1 = wp[1], w2 = wp[2];
#pragma unroll
                    for (int p = 0; p < 4; p++){
                        fma2(acc[i][0][p], pea[p],   w0);
                        fma2(acc[i][0][p], poa[p],   w1);
                        fma2(acc[i][0][p], pea[p+1], w2);
                        fma2(acc[i][1][p], peb[p],   w0);
                        fma2(acc[i][1][p], pob[p],   w1);
                        fma2(acc[i][1][p], peb[p+1], w2);
                    }
                }
                if (kh < 2){
#pragma unroll
                    for (int p = 0; p < 5; p++) pea[p] = peb[p];
#pragma unroll
                    for (int p = 0; p < 4; p++) poa[p] = pob[p];
                    const float* rr = sp + (kh+2)*33;
                    float rv[10];
#pragma unroll
                    for (int j = 0; j < 10; j++) rv[j] = rr[j];
#pragma unroll
                    for (int p = 0; p < 5; p++) peb[p] = pack2(rv[2*p], rv[2*p+1]);
#pragma unroll
                    for (int p = 0; p < 4; p++) pob[p] = pack2(rv[2*p+1], rv[2*p+2]);
                }
            }
        }
    }
#pragma unroll
    for (int i = 0; i < 4; i++){
        int oc = ocbase + q*4 + i;
        float sc = g_scale_s[oc], bi = g_bias_s[oc];
#pragma unroll
        for (int r2 = 0; r2 < 2; r2++){
            int orow = row0 + rp*2 + r2;
            if (orow < 29){
                float* op = g_s + (((size_t)b*C + oc)*29 + orow)*29;
#pragma unroll
                for (int p = 0; p < 4; p++){
                    float2 f = unpk(acc[i][r2][p]);
                    int col = c*8 + 2*p;
                    if (col < 29){ float v = fmaf(sc, f.x, bi); op[col]   = v > 0.f ? v : 0.f; }
                    if (col+1 < 29){ float v = fmaf(sc, f.y, bi); op[col+1] = v > 0.f ? v : 0.f; }
                }
            }
        }
    }
}

// ---------------- corr v2: warp = channel, lane = output row, f32x2 --------------
template<int TS, int PAD, int OS>
__global__ void __launch_bounds__(256) corr_v2(const float* __restrict__ t,
                                               float* __restrict__ out){
    constexpr int R = OS + TS - 1;          // padded rows
    constexpr int STRIDE = 35;
    constexpr int NPAIR = (OS + 1) / 2;
    constexpr int VW = 2*NPAIR + TS - 1;    // values needed per row
    constexpr int NPE = VW / 2;
    __shared__ float s_pad[8 * R * STRIDE];
    __shared__ float s_t[8 * TS * TS];
    int tid = threadIdx.x;
    int wrp = tid >> 5, lane = tid & 31;
    int b = blockIdx.x;
    int c0 = blockIdx.y * 8;

#pragma unroll 1
    for (int idx = tid; idx < 8 * R * STRIDE; idx += 256) s_pad[idx] = 0.f;
    __syncthreads();
    const float* sb = g_s + ((size_t)b*C + c0) * 841;
#pragma unroll 1
    for (int idx = tid; idx < 8 * 841; idx += 256){
        int ch = idx / 841, rem = idx - ch*841;
        int row = rem / 29, col = rem - row*29;
        s_pad[ch*R*STRIDE + (row + PAD)*STRIDE + col + PAD] = sb[ch*841 + rem];
    }
    const float* tb = t + ((size_t)b*C + c0) * TS * TS;
#pragma unroll 1
    for (int idx = tid; idx < 8 * TS * TS; idx += 256) s_t[idx] = tb[idx];
    __syncthreads();

    if (lane < OS){
        const float* sp = s_pad + wrp*R*STRIDE + lane*STRIDE;
        const float* tp = s_t + wrp*TS*TS;
        u64 a[NPAIR];
#pragma unroll
        for (int p = 0; p < NPAIR; p++) a[p] = 0ull;
#pragma unroll
        for (int trow = 0; trow < TS; trow++){
            u64 wd[TS];
#pragma unroll
            for (int j = 0; j < TS; j++) wd[j] = dup2(tp[trow*TS + j]);
            float v[VW];
#pragma unroll
            for (int k = 0; k < VW; k++) v[k] = sp[trow*STRIDE + k];
            u64 pe[NPE], po[NPE-1];
#pragma unroll
            for (int k = 0; k < NPE; k++) pe[k] = pack2(v[2*k], v[2*k+1]);
#pragma unroll
            for (int k = 0; k < NPE-1; k++) po[k] = pack2(v[2*k+1], v[2*k+2]);
#pragma unroll
            for (int j = 0; j < TS; j++){
                if (j & 1){
#pragma unroll
                    for (int p = 0; p < NPAIR; p++) fma2(a[p], po[p + (j>>1)], wd[j]);
                } else {
#pragma unroll
                    for (int p = 0; p < NPAIR; p++) fma2(a[p], pe[p + (j>>1)], wd[j]);
                }
            }
        }
        float* op = out + (((size_t)b*C + c0 + wrp)*OS + lane)*OS;
#pragma unroll
        for (int p = 0; p < NPAIR; p++){
            float2 f = unpk(a[p]);
            op[2*p] = f.x;
            if (2*p + 1 < OS) op[2*p + 1] = f.y;
        }
    }
}

// ---------------- head v2: thread = 4 n x 16 px --------------------------------
__global__ void __launch_bounds__(256) head_kernel(const float* __restrict__ x, int HW,
                                                   const float* __restrict__ w1,
                                                   const float* __restrict__ w2,
                                                   const float* __restrict__ b2,
                                                   float* __restrict__ out){
    __shared__ __align__(16) float s_w[32 * 260];
    __shared__ __align__(16) float s_x[32 * 64];
    __shared__ float s_red[8][16];
    int tid = threadIdx.x;
    int nq = tid & 63;          // n group: n0 = nq*4
    int pg = tid >> 6;          // px group: px = p0 + pg*16
    int n0 = nq * 4;
    int b = blockIdx.y;
    int p0 = blockIdx.x * 64;
    const float* xb = x + (size_t)b * C * HW;

    u64 acc[4][8];
#pragma unroll
    for (int i = 0; i < 4; i++)
#pragma unroll
        for (int p = 0; p < 8; p++) acc[i][p] = 0ull;

    for (int k0 = 0; k0 < C; k0 += 32){
        __syncthreads();
#pragma unroll 1
        for (int idx = tid; idx < 8192; idx += 256){
            int kk = idx & 31, n = idx >> 5;
            s_w[kk*260 + n] = w1[n*C + k0 + kk];
        }
#pragma unroll 1
        for (int idx = tid; idx < 2048; idx += 256){
            int p = idx & 63, kk = idx >> 6;
            int gp = p0 + p;
            s_x[kk*64 + p] = (gp < HW) ? xb[(k0+kk)*HW + gp] : 0.f;
        }
        __syncthreads();
#pragma unroll 4
        for (int kk = 0; kk < 32; kk++){
            float4 wf = *(const float4*)&s_w[kk*260 + n0];
            u64 w0 = dup2(wf.x), w1d = dup2(wf.y), w2d = dup2(wf.z), w3d = dup2(wf.w);
            const u64* xp = (const u64*)(s_x + kk*64) + pg*8;
            u64 xv[8];
#pragma unroll
            for (int p = 0; p < 8; p++) xv[p] = xp[p];
#pragma unroll
            for (int p = 0; p < 8; p++){
                fma2(acc[0][p], xv[p], w0);
                fma2(acc[1][p], xv[p], w1d);
                fma2(acc[2][p], xv[p], w2d);
                fma2(acc[3][p], xv[p], w3d);
            }
        }
    }

    // BN + ReLU + * w2[n], sum over this thread's 4 n
    u64 psum[8];
#pragma unroll
    for (int p = 0; p < 8; p++) psum[p] = 0ull;
#pragma unroll
    for (int i = 0; i < 4; i++){
        float sc = g_scale_1[n0+i], bi = g_bias_1[n0+i], wv = w2[n0+i];
#pragma unroll
        for (int p = 0; p < 8; p++){
            float2 f = unpk(acc[i][p]);
            f.x = fmaxf(fmaf(sc, f.x, bi), 0.f) * wv;
            f.y = fmaxf(fmaf(sc, f.y, bi), 0.f) * wv;
            psum[p] = add2(psum[p], pack2(f.x, f.y));
        }
    }
    // reduce across 32 lanes (covers 32 n-groups); warps pair up per pg.
    int lane = tid & 31, wrp = tid >> 5;
#pragma unroll
    for (int p = 0; p < 8; p++){
        u64 v = psum[p];
        v = add2(v, __shfl_xor_sync(0xffffffffu, v, 16));
        v = add2(v, __shfl_xor_sync(0xffffffffu, v, 8));
        v = add2(v, __shfl_xor_sync(0xffffffffu, v, 4));
        v = add2(v, __shfl_xor_sync(0xffffffffu, v, 2));
        v = add2(v, __shfl_xor_sync(0xffffffffu, v, 1));
        psum[p] = v;
    }
    if (lane == 0){
#pragma unroll
        for (int p = 0; p < 8; p++){
            float2 f = unpk(psum[p]);
            s_red[wrp][2*p] = f.x;
            s_red[wrp][2*p+1] = f.y;
        }
    }
    __syncthreads();
    if (tid < 64){
        int pg2 = tid >> 4, j = tid & 15;
        float v = s_red[2*pg2][j] + s_red[2*pg2+1][j];
        int gp = p0 + pg2*16 + j;
        if (gp < HW)
            out[(size_t)b*HW + gp] = 1.f / (1.f + expf(-(v + b2[0])));
    }
}

// ---------------- launch ----------------
extern "C" void kernel_launch(void* const* d_in, const int* in_sizes, int n_in,
                              void* d_out, int out_size){
    const float* large  = (const float*)d_in[0];
    const float* medium = (const float*)d_in[1];
    const float* small  = (const float*)d_in[2];
    const float* search = (const float*)d_in[3];
    const float* wt  = (const float*)d_in[4];
    const float* bt  = (const float*)d_in[5];
    const float* gt  = (const float*)d_in[6];
    const float* bet = (const float*)d_in[7];
    const float* mt  = (const float*)d_in[8];
    const float* vt  = (const float*)d_in[9];
    const float* ws  = (const float*)d_in[10];
    const float* bs  = (const float*)d_in[11];
    const float* gs  = (const float*)d_in[12];
    const float* bes = (const float*)d_in[13];
    const float* ms  = (const float*)d_in[14];
    const float* vs  = (const float*)d_in[15];
    const float* w1  = (const float*)d_in[16];
    const float* b1  = (const float*)d_in[17];
    const float* g1  = (const float*)d_in[18];
    const float* be1 = (const float*)d_in[19];
    const float* m1  = (const float*)d_in[20];
    const float* v1  = (const float*)d_in[21];
    const float* w2  = (const float*)d_in[22];
    const float* b2  = (const float*)d_in[23];
    float* out = (float*)d_out;

    float *lf, *mf, *sf, *lc, *mc, *sc;
    cudaGetSymbolAddress((void**)&lf, g_lf);
    cudaGetSymbolAddress((void**)&mf, g_mf);
    cudaGetSymbolAddress((void**)&sf, g_sf);
    cudaGetSymbolAddress((void**)&lc, g_lc);
    cudaGetSymbolAddress((void**)&mc, g_mc);
    cudaGetSymbolAddress((void**)&sc, g_sc);

    prep_kernel<<<1, 256>>>(bt, gt, bet, mt, vt, bs, gs, bes, ms, vs, b1, g1, be1, m1, v1);

    tmpl_all<<<dim3(64, 4), 512>>>(large, medium, small, wt, lf, mf, sf);
    conv_search<<<dim3(64, 8, 2), 256>>>(search, ws);

    corr_v2<7, 2, 27><<<dim3(64, 32), 256>>>(lf, lc);
    corr_v2<5, 0, 25><<<dim3(64, 32), 256>>>(mf, mc);
    corr_v2<3, 0, 27><<<dim3(64, 32), 256>>>(sf, sc);

    head_kernel<<<dim3(12, 64), 256>>>(lc, 729, w1, w2, b2, out);
    head_kernel<<<dim3(10, 64), 256>>>(mc, 625, w1, w2, b2, out + 64*729);
    head_kernel<<<dim3(12, 64), 256>>>(sc, 729, w1, w2, b2, out + 64*729 + 64*625);
}

// round 6
// speedup vs baseline: 1.2841x; 1.1950x over previous
#include <cuda_runtime.h>
#include <math.h>

#define B 64
#define C 256

typedef unsigned long long u64;
typedef unsigned int u32;

// ---------------- f32x2 packed-math helpers ----------------
__device__ __forceinline__ u64 pack2(float lo, float hi){
    u64 r; asm("mov.b64 %0, {%1, %2};" : "=l"(r) : "f"(lo), "f"(hi)); return r;
}
__device__ __forceinline__ u64 dup2(float v){
    u64 r; asm("mov.b64 %0, {%1, %1};" : "=l"(r) : "f"(v)); return r;
}
__device__ __forceinline__ void fma2(u64 &d, u64 a, u64 b){
    asm("fma.rn.f32x2 %0, %1, %2, %0;" : "+l"(d) : "l"(a), "l"(b));
}
__device__ __forceinline__ u64 add2(u64 a, u64 b){
    u64 d; asm("add.rn.f32x2 %0, %1, %2;" : "=l"(d) : "l"(a), "l"(b)); return d;
}
__device__ __forceinline__ float2 unpk(u64 v){
    float2 f; asm("mov.b64 {%0, %1}, %2;" : "=f"(f.x), "=f"(f.y) : "l"(v)); return f;
}
__device__ __forceinline__ u32 tf32r(float v){
    u32 r; asm("cvt.rna.tf32.f32 %0, %1;" : "=r"(r) : "f"(v)); return r;
}

// ---------------- scratch ----------------
__device__ float g_lf[B*C*7*7];
__device__ float g_mf[B*C*5*5];
__device__ float g_sf[B*C*3*3];
__device__ float g_s [B*C*29*29];
__device__ float g_lc[B*C*27*27];
__device__ float g_mc[B*C*25*25];
__device__ float g_sc[B*C*27*27];
__device__ float g_wt[9*C*C];          // transposed search weights [khw][oc][ic]
__device__ float g_scale_t[C], g_bias_t[C];
__device__ float g_scale_s[C], g_bias_s[C];
__device__ float g_scale_1[C], g_bias_1[C];

// ---------------- BN folding ----------------
__global__ void prep_kernel(const float* bt,const float* gt,const float* bet,const float* mt,const float* vt,
                            const float* bs,const float* gs,const float* bes,const float* ms,const float* vs,
                            const float* b1,const float* g1,const float* be1,const float* m1,const float* v1){
    int c = threadIdx.x;
    { float inv = gt[c]*rsqrtf(vt[c]+1e-5f); g_scale_t[c]=inv; g_bias_t[c]=bt[c]*inv + bet[c] - mt[c]*inv; }
    { float inv = gs[c]*rsqrtf(vs[c]+1e-5f); g_scale_s[c]=inv; g_bias_s[c]=bs[c]*inv + bes[c] - ms[c]*inv; }
    { float inv = g1[c]*rsqrtf(v1[c]+1e-5f); g_scale_1[c]=inv; g_bias_1[c]=b1[c]*inv + be1[c] - m1[c]*inv; }
}

// ---------------- weight transpose for search conv ----------------
__global__ void wt_trans(const float* __restrict__ w){
    int idx = blockIdx.x * 256 + threadIdx.x;
    if (idx < 9*C*C){
        int khw = idx % 9;
        int rest = idx / 9;          // oc*256 + ic
        int ic = rest & 255;
        int oc = rest >> 8;
        g_wt[khw*C*C + oc*C + ic] = w[idx];
    }
}

// ---------------- merged template conv 3x3 + BN + ReLU, f32x2 ----------------
template<int W, int NP>
__device__ __forceinline__ void row3(const float* ip, const u64* wdA, const u64* wdB,
                                     u64* aA, u64* aB){
#pragma unroll
    for (int kh = 0; kh < 3; kh++){
        float rv[2*NP+2];
#pragma unroll
        for (int j = 0; j < 2*NP+2; j++) rv[j] = ip[kh*W + j];
        u64 pe[NP+1], po[NP];
#pragma unroll
        for (int p = 0; p <= NP; p++) pe[p] = pack2(rv[2*p], rv[2*p+1]);
#pragma unroll
        for (int p = 0; p < NP; p++) po[p] = pack2(rv[2*p+1], rv[2*p+2]);
#pragma unroll
        for (int p = 0; p < NP; p++){
            fma2(aA[p], pe[p],   wdA[kh*3+0]);
            fma2(aA[p], po[p],   wdA[kh*3+1]);
            fma2(aA[p], pe[p+1], wdA[kh*3+2]);
            fma2(aB[p], pe[p],   wdB[kh*3+0]);
            fma2(aB[p], po[p],   wdB[kh*3+1]);
            fma2(aB[p], pe[p+1], wdB[kh*3+2]);
        }
    }
}

template<int OH, int NP>
__device__ __forceinline__ void tmpl_store(float* out, int b, int oc0, int row,
                                           const u64* aA, const u64* aB){
    float scA = g_scale_t[oc0],   biA = g_bias_t[oc0];
    float scB = g_scale_t[oc0+1], biB = g_bias_t[oc0+1];
    float* pA = out + (((size_t)b*C + oc0  )*OH + row)*OH;
    float* pB = out + (((size_t)b*C + oc0+1)*OH + row)*OH;
#pragma unroll
    for (int p = 0; p < NP; p++){
        float2 fa = unpk(aA[p]), fb = unpk(aB[p]);
        int col = 2*p;
        if (col < OH){
            float va = fmaf(scA, fa.x, biA); pA[col] = va > 0.f ? va : 0.f;
            float vb = fmaf(scB, fb.x, biB); pB[col] = vb > 0.f ? vb : 0.f;
        }
        if (col+1 < OH){
            float va = fmaf(scA, fa.y, biA); pA[col+1] = va > 0.f ? va : 0.f;
            float vb = fmaf(scB, fb.y, biB); pB[col+1] = vb > 0.f ? vb : 0.f;
        }
    }
}

__global__ void __launch_bounds__(512) tmpl_all(const float* __restrict__ lin,
                                                const float* __restrict__ min_,
                                                const float* __restrict__ sin_,
                                                const float* __restrict__ w,
                                                float* lo, float* mo, float* so){
    __shared__ __align__(16) float s_in[16*155 + 4];
    __shared__ __align__(16) float s_w[144*66];
    int tid = threadIdx.x;
    int ocp = tid & 31, slot = tid >> 5;
    int b = blockIdx.x, ocbase = blockIdx.y * 64;
    int oc0 = ocbase + ocp*2;

    u64 aA[4] = {0,0,0,0}, aB[4] = {0,0,0,0};

    for (int ic0 = 0; ic0 < C; ic0 += 16){
        __syncthreads();
#pragma unroll 1
        for (int idx = tid; idx < 16*155; idx += 512){
            int ic = idx / 155, r = idx % 155;
            size_t cb = (size_t)b*C + ic0 + ic;
            float v;
            if (r < 81)       v = lin [cb*81 + r];
            else if (r < 130) v = min_[cb*49 + (r-81)];
            else              v = sin_[cb*25 + (r-130)];
            s_in[ic*155 + r] = v;
        }
#pragma unroll 1
        for (int idx = tid; idx < 64*144; idx += 512){
            int oc = idx / 144, r = idx % 144;
            s_w[r*66 + oc] = w[(size_t)(ocbase+oc)*2304 + (size_t)ic0*9 + r];
        }
        __syncthreads();

        if (slot < 7){
            int row = slot;
#pragma unroll 1
            for (int ic = 0; ic < 16; ic++){
                u64 wdA[9], wdB[9];
#pragma unroll
                for (int k = 0; k < 9; k++){
                    u64 pr = *(const u64*)&s_w[(ic*9+k)*66 + ocp*2];
                    float2 f = unpk(pr);
                    wdA[k] = dup2(f.x); wdB[k] = dup2(f.y);
                }
                row3<9,4>(s_in + ic*155 + row*9, wdA, wdB, aA, aB);
            }
        } else if (slot < 12){
            int row = slot - 7;
#pragma unroll 1
            for (int ic = 0; ic < 16; ic++){
                u64 wdA[9], wdB[9];
#pragma unroll
                for (int k = 0; k < 9; k++){
                    u64 pr = *(const u64*)&s_w[(ic*9+k)*66 + ocp*2];
                    float2 f = unpk(pr);
                    wdA[k] = dup2(f.x); wdB[k] = dup2(f.y);
                }
                row3<7,3>(s_in + ic*155 + 81 + row*7, wdA, wdB, aA, aB);
            }
        } else if (slot < 15){
            int row = slot - 12;
#pragma unroll 1
            for (int ic = 0; ic < 16; ic++){
                u64 wdA[9], wdB[9];
#pragma unroll
                for (int k = 0; k < 9; k++){
                    u64 pr = *(const u64*)&s_w[(ic*9+k)*66 + ocp*2];
                    float2 f = unpk(pr);
                    wdA[k] = dup2(f.x); wdB[k] = dup2(f.y);
                }
                row3<5,2>(s_in + ic*155 + 130 + row*5, wdA, wdB, aA, aB);
            }
        }
    }

    if (slot < 7)       tmpl_store<7,4>(lo, b, oc0, slot,      aA, aB);
    else if (slot < 12) tmpl_store<5,3>(mo, b, oc0, slot - 7,  aA, aB);
    else if (slot < 15) tmpl_store<3,2>(so, b, oc0, slot - 12, aA, aB);
}

// ---------------- search conv via 3xTF32 mma.sync implicit GEMM ----------------
// grid (64 b, 7 px-tiles, 4 oc-tiles), 256 thr = 8 warps (4 M x 2 N).
// block tile: 128 px x 64 oc; warp tile 32 px x 32 oc via m16n8k8.
// A-tile stages 8 input rows (248 values): a 128-px tile can span 6 output rows
// (max r - r_first = 5), needing input rows r_first..r_first+7. rc0+sh <= 247.
#define SA_ROWS 248
#define SA_N (SA_ROWS*36)
#define SB_N (64*36)
#define CSM_BYTES ((2*SA_N + 2*SB_N) * 4)

__global__ void __launch_bounds__(256) conv_search_mma(const float* __restrict__ in){
    extern __shared__ u32 smem_dyn[];
    u32* sa_hi = smem_dyn;
    u32* sa_lo = sa_hi + SA_N;
    u32* sb_hi = sa_lo + SA_N;
    u32* sb_lo = sb_hi + SB_N;

    int tid = threadIdx.x;
    int lane = tid & 31, wid = tid >> 5;
    int g = lane >> 2, t = lane & 3;
    int wm = wid & 3, wn = wid >> 2;
    int b = blockIdx.x;
    int pstart = blockIdx.y * 128;
    int ocb0 = blockIdx.z * 64;
    int r_first = pstart / 29;

    int rc0[2][2], pxv[2][2];
    bool pvalid[2][2];
#pragma unroll
    for (int mf = 0; mf < 2; mf++)
#pragma unroll
        for (int h = 0; h < 2; h++){
            int px = pstart + wm*32 + mf*16 + g + h*8;
            pvalid[mf][h] = (px < 841);
            int pxc = px < 841 ? px : 840;
            pxv[mf][h] = pxc;
            int r = pxc / 29, c = pxc - r*29;
            rc0[mf][h] = (r - r_first)*31 + c;
        }

    float acc[2][4][4];
#pragma unroll
    for (int mf = 0; mf < 2; mf++)
#pragma unroll
        for (int nf = 0; nf < 4; nf++)
#pragma unroll
            for (int i = 0; i < 4; i++) acc[mf][nf][i] = 0.f;

    const float* inb = in + (size_t)b * C * 961;

    for (int ic0 = 0; ic0 < C; ic0 += 32){
        __syncthreads();
#pragma unroll 1
        for (int idx = tid; idx < 32*SA_ROWS; idx += 256){
            int ic = idx / SA_ROWS, rc = idx - ic*SA_ROWS;
            int gidx = r_first*31 + rc;
            float v = (gidx < 961) ? inb[(ic0+ic)*961 + gidx] : 0.f;
            u32 hb = tf32r(v);
            sa_hi[rc*36 + ic] = hb;
            sa_lo[rc*36 + ic] = tf32r(v - __uint_as_float(hb));
        }
#pragma unroll 1
        for (int khw = 0; khw < 9; khw++){
            __syncthreads();
            const float* wp = g_wt + (size_t)khw*C*C + (size_t)ocb0*C + ic0;
#pragma unroll 1
            for (int idx = tid; idx < 2048; idx += 256){
                int oc = idx >> 5, ic = idx & 31;
                float v = wp[oc*C + ic];
                u32 hb = tf32r(v);
                sb_hi[oc*36 + ic] = hb;
                sb_lo[oc*36 + ic] = tf32r(v - __uint_as_float(hb));
            }
            __syncthreads();
            int kh = khw / 3, kw = khw - kh*3;
            int sh = kh*31 + kw;
#pragma unroll
            for (int ks = 0; ks < 4; ks++){
                int k0 = ks * 8;
                u32 bh0[4], bh1[4], bl0[4], bl1[4];
#pragma unroll
                for (int nf = 0; nf < 4; nf++){
                    int ocl = wn*32 + nf*8 + g;
                    bh0[nf] = sb_hi[ocl*36 + k0 + t];
                    bh1[nf] = sb_hi[ocl*36 + k0 + t + 4];
                    bl0[nf] = sb_lo[ocl*36 + k0 + t];
                    bl1[nf] = sb_lo[ocl*36 + k0 + t + 4];
                }
#pragma unroll
                for (int mf = 0; mf < 2; mf++){
                    int i0 = (rc0[mf][0] + sh)*36 + k0 + t;
                    int i1 = (rc0[mf][1] + sh)*36 + k0 + t;
                    u32 ah0 = sa_hi[i0], ah1 = sa_hi[i1];
                    u32 ah2 = sa_hi[i0+4], ah3 = sa_hi[i1+4];
                    u32 al0 = sa_lo[i0], al1 = sa_lo[i1];
                    u32 al2 = sa_lo[i0+4], al3 = sa_lo[i1+4];
#pragma unroll
                    for (int nf = 0; nf < 4; nf++){
                        asm volatile(
                            "mma.sync.aligned.m16n8k8.row.col.f32.tf32.tf32.f32 "
                            "{%0,%1,%2,%3}, {%4,%5,%6,%7}, {%8,%9}, {%0,%1,%2,%3};"
                            : "+f"(acc[mf][nf][0]), "+f"(acc[mf][nf][1]),
                              "+f"(acc[mf][nf][2]), "+f"(acc[mf][nf][3])
                            : "r"(ah0), "r"(ah1), "r"(ah2), "r"(ah3),
                              "r"(bh0[nf]), "r"(bh1[nf]));
                        asm volatile(
                            "mma.sync.aligned.m16n8k8.row.col.f32.tf32.tf32.f32 "
                            "{%0,%1,%2,%3}, {%4,%5,%6,%7}, {%8,%9}, {%0,%1,%2,%3};"
                            : "+f"(acc[mf][nf][0]), "+f"(acc[mf][nf][1]),
                              "+f"(acc[mf][nf][2]), "+f"(acc[mf][nf][3])
                            : "r"(ah0), "r"(ah1), "r"(ah2), "r"(ah3),
                              "r"(bl0[nf]), "r"(bl1[nf]));
                        asm volatile(
                            "mma.sync.aligned.m16n8k8.row.col.f32.tf32.tf32.f32 "
                            "{%0,%1,%2,%3}, {%4,%5,%6,%7}, {%8,%9}, {%0,%1,%2,%3};"
                            : "+f"(acc[mf][nf][0]), "+f"(acc[mf][nf][1]),
                              "+f"(acc[mf][nf][2]), "+f"(acc[mf][nf][3])
                            : "r"(al0), "r"(al1), "r"(al2), "r"(al3),
                              "r"(bh0[nf]), "r"(bh1[nf]));
                    }
                }
            }
        }
    }

    // epilogue: BN + ReLU, scatter to g_s[b][oc][px]
#pragma unroll
    for (int nf = 0; nf < 4; nf++){
        int oc0 = ocb0 + wn*32 + nf*8 + 2*t;
        int oc1 = oc0 + 1;
        float sc0 = g_scale_s[oc0], bi0 = g_bias_s[oc0];
        float sc1 = g_scale_s[oc1], bi1 = g_bias_s[oc1];
#pragma unroll
        for (int mf = 0; mf < 2; mf++){
            if (pvalid[mf][0]){
                float v0 = fmaf(sc0, acc[mf][nf][0], bi0);
                float v1 = fmaf(sc1, acc[mf][nf][1], bi1);
                g_s[((size_t)b*C + oc0)*841 + pxv[mf][0]] = v0 > 0.f ? v0 : 0.f;
                g_s[((size_t)b*C + oc1)*841 + pxv[mf][0]] = v1 > 0.f ? v1 : 0.f;
            }
            if (pvalid[mf][1]){
                float v2 = fmaf(sc0, acc[mf][nf][2], bi0);
                float v3 = fmaf(sc1, acc[mf][nf][3], bi1);
                g_s[((size_t)b*C + oc0)*841 + pxv[mf][1]] = v2 > 0.f ? v2 : 0.f;
                g_s[((size_t)b*C + oc1)*841 + pxv[mf][1]] = v3 > 0.f ? v3 : 0.f;
            }
        }
    }
}

// ---------------- corr v2: warp = channel, lane = output row, f32x2 --------------
template<int TS, int PAD, int OS>
__global__ void __launch_bounds__(256) corr_v2(const float* __restrict__ t,
                                               float* __restrict__ out){
    constexpr int R = OS + TS - 1;
    constexpr int STRIDE = 35;
    constexpr int NPAIR = (OS + 1) / 2;
    constexpr int VW = 2*NPAIR + TS - 1;
    constexpr int NPE = VW / 2;
    __shared__ float s_pad[8 * R * STRIDE];
    __shared__ float s_t[8 * TS * TS];
    int tid = threadIdx.x;
    int wrp = tid >> 5, lane = tid & 31;
    int b = blockIdx.x;
    int c0 = blockIdx.y * 8;

#pragma unroll 1
    for (int idx = tid; idx < 8 * R * STRIDE; idx += 256) s_pad[idx] = 0.f;
    __syncthreads();
    const float* sb = g_s + ((size_t)b*C + c0) * 841;
#pragma unroll 1
    for (int idx = tid; idx < 8 * 841; idx += 256){
        int ch = idx / 841, rem = idx - ch*841;
        int row = rem / 29, col = rem - row*29;
        s_pad[ch*R*STRIDE + (row + PAD)*STRIDE + col + PAD] = sb[ch*841 + rem];
    }
    const float* tb = t + ((size_t)b*C + c0) * TS * TS;
#pragma unroll 1
    for (int idx = tid; idx < 8 * TS * TS; idx += 256) s_t[idx] = tb[idx];
    __syncthreads();

    if (lane < OS){
        const float* sp = s_pad + wrp*R*STRIDE + lane*STRIDE;
        const float* tp = s_t + wrp*TS*TS;
        u64 a[NPAIR];
#pragma unroll
        for (int p = 0; p < NPAIR; p++) a[p] = 0ull;
#pragma unroll
        for (int trow = 0; trow < TS; trow++){
            u64 wd[TS];
#pragma unroll
            for (int j = 0; j < TS; j++) wd[j] = dup2(tp[trow*TS + j]);
            float v[VW];
#pragma unroll
            for (int k = 0; k < VW; k++) v[k] = sp[trow*STRIDE + k];
            u64 pe[NPE], po[NPE-1];
#pragma unroll
            for (int k = 0; k < NPE; k++) pe[k] = pack2(v[2*k], v[2*k+1]);
#pragma unroll
            for (int k = 0; k < NPE-1; k++) po[k] = pack2(v[2*k+1], v[2*k+2]);
#pragma unroll
            for (int j = 0; j < TS; j++){
                if (j & 1){
#pragma unroll
                    for (int p = 0; p < NPAIR; p++) fma2(a[p], po[p + (j>>1)], wd[j]);
                } else {
#pragma unroll
                    for (int p = 0; p < NPAIR; p++) fma2(a[p], pe[p + (j>>1)], wd[j]);
                }
            }
        }
        float* op = out + (((size_t)b*C + c0 + wrp)*OS + lane)*OS;
#pragma unroll
        for (int p = 0; p < NPAIR; p++){
            float2 f = unpk(a[p]);
            op[2*p] = f.x;
            if (2*p + 1 < OS) op[2*p + 1] = f.y;
        }
    }
}

// ---------------- head v2: thread = 4 n x 16 px --------------------------------
__global__ void __launch_bounds__(256) head_kernel(const float* __restrict__ x, int HW,
                                                   const float* __restrict__ w1,
                                                   const float* __restrict__ w2,
                                                   const float* __restrict__ b2,
                                                   float* __restrict__ out){
    __shared__ __align__(16) float s_w[32 * 260];
    __shared__ __align__(16) float s_x[32 * 64];
    __shared__ float s_red[8][16];
    int tid = threadIdx.x;
    int nq = tid & 63;
    int pg = tid >> 6;
    int n0 = nq * 4;
    int b = blockIdx.y;
    int p0 = blockIdx.x * 64;
    const float* xb = x + (size_t)b * C * HW;

    u64 acc[4][8];
#pragma unroll
    for (int i = 0; i < 4; i++)
#pragma unroll
        for (int p = 0; p < 8; p++) acc[i][p] = 0ull;

    for (int k0 = 0; k0 < C; k0 += 32){
        __syncthreads();
#pragma unroll 1
        for (int idx = tid; idx < 8192; idx += 256){
            int kk = idx & 31, n = idx >> 5;
            s_w[kk*260 + n] = w1[n*C + k0 + kk];
        }
#pragma unroll 1
        for (int idx = tid; idx < 2048; idx += 256){
            int p = idx & 63, kk = idx >> 6;
            int gp = p0 + p;
            s_x[kk*64 + p] = (gp < HW) ? xb[(k0+kk)*HW + gp] : 0.f;
        }
        __syncthreads();
#pragma unroll 4
        for (int kk = 0; kk < 32; kk++){
            float4 wf = *(const float4*)&s_w[kk*260 + n0];
            u64 w0 = dup2(wf.x), w1d = dup2(wf.y), w2d = dup2(wf.z), w3d = dup2(wf.w);
            const u64* xp = (const u64*)(s_x + kk*64) + pg*8;
            u64 xv[8];
#pragma unroll
            for (int p = 0; p < 8; p++) xv[p] = xp[p];
#pragma unroll
            for (int p = 0; p < 8; p++){
                fma2(acc[0][p], xv[p], w0);
                fma2(acc[1][p], xv[p], w1d);
                fma2(acc[2][p], xv[p], w2d);
                fma2(acc[3][p], xv[p], w3d);
            }
        }
    }

    u64 psum[8];
#pragma unroll
    for (int p = 0; p < 8; p++) psum[p] = 0ull;
#pragma unroll
    for (int i = 0; i < 4; i++){
        float sc = g_scale_1[n0+i], bi = g_bias_1[n0+i], wv = w2[n0+i];
#pragma unroll
        for (int p = 0; p < 8; p++){
            float2 f = unpk(acc[i][p]);
            f.x = fmaxf(fmaf(sc, f.x, bi), 0.f) * wv;
            f.y = fmaxf(fmaf(sc, f.y, bi), 0.f) * wv;
            psum[p] = add2(psum[p], pack2(f.x, f.y));
        }
    }
    int lane = tid & 31, wrp = tid >> 5;
#pragma unroll
    for (int p = 0; p < 8; p++){
        u64 v = psum[p];
        v = add2(v, __shfl_xor_sync(0xffffffffu, v, 16));
        v = add2(v, __shfl_xor_sync(0xffffffffu, v, 8));
        v = add2(v, __shfl_xor_sync(0xffffffffu, v, 4));
        v = add2(v, __shfl_xor_sync(0xffffffffu, v, 2));
        v = add2(v, __shfl_xor_sync(0xffffffffu, v, 1));
        psum[p] = v;
    }
    if (lane == 0){
#pragma unroll
        for (int p = 0; p < 8; p++){
            float2 f = unpk(psum[p]);
            s_red[wrp][2*p] = f.x;
            s_red[wrp][2*p+1] = f.y;
        }
    }
    __syncthreads();
    if (tid < 64){
        int pg2 = tid >> 4, j = tid & 15;
        float v = s_red[2*pg2][j] + s_red[2*pg2+1][j];
        int gp = p0 + pg2*16 + j;
        if (gp < HW)
            out[(size_t)b*HW + gp] = 1.f / (1.f + expf(-(v + b2[0])));
    }
}

// ---------------- launch ----------------
extern "C" void kernel_launch(void* const* d_in, const int* in_sizes, int n_in,
                              void* d_out, int out_size){
    const float* large  = (const float*)d_in[0];
    const float* medium = (const float*)d_in[1];
    const float* small  = (const float*)d_in[2];
    const float* search = (const float*)d_in[3];
    const float* wt  = (const float*)d_in[4];
    const float* bt  = (const float*)d_in[5];
    const float* gt  = (const float*)d_in[6];
    const float* bet = (const float*)d_in[7];
    const float* mt  = (const float*)d_in[8];
    const float* vt  = (const float*)d_in[9];
    const float* ws  = (const float*)d_in[10];
    const float* bs  = (const float*)d_in[11];
    const float* gs  = (const float*)d_in[12];
    const float* bes = (const float*)d_in[13];
    const float* ms  = (const float*)d_in[14];
    const float* vs  = (const float*)d_in[15];
    const float* w1  = (const float*)d_in[16];
    const float* b1  = (const float*)d_in[17];
    const float* g1  = (const float*)d_in[18];
    const float* be1 = (const float*)d_in[19];
    const float* m1  = (const float*)d_in[20];
    const float* v1  = (const float*)d_in[21];
    const float* w2  = (const float*)d_in[22];
    const float* b2  = (const float*)d_in[23];
    float* out = (float*)d_out;

    float *lf, *mf, *sf, *lc, *mc, *sc;
    cudaGetSymbolAddress((void**)&lf, g_lf);
    cudaGetSymbolAddress((void**)&mf, g_mf);
    cudaGetSymbolAddress((void**)&sf, g_sf);
    cudaGetSymbolAddress((void**)&lc, g_lc);
    cudaGetSymbolAddress((void**)&mc, g_mc);
    cudaGetSymbolAddress((void**)&sc, g_sc);

    static int smem_set = 0;
    if (!smem_set){
        cudaFuncSetAttribute(conv_search_mma,
                             cudaFuncAttributeMaxDynamicSharedMemorySize, CSM_BYTES);
        smem_set = 1;
    }

    prep_kernel<<<1, 256>>>(bt, gt, bet, mt, vt, bs, gs, bes, ms, vs, b1, g1, be1, m1, v1);
    wt_trans<<<(9*C*C + 255)/256, 256>>>(ws);

    tmpl_all<<<dim3(64, 4), 512>>>(large, medium, small, wt, lf, mf, sf);
    conv_search_mma<<<dim3(64, 7, 4), 256, CSM_BYTES>>>(search);

    corr_v2<7, 2, 27><<<dim3(64, 32), 256>>>(lf, lc);
    corr_v2<5, 0, 25><<<dim3(64, 32), 256>>>(mf, mc);
    corr_v2<3, 0, 27><<<dim3(64, 32), 256>>>(sf, sc);

    head_kernel<<<dim3(12, 64), 256>>>(lc, 729, w1, w2, b2, out);
    head_kernel<<<dim3(10, 64), 256>>>(mc, 625, w1, w2, b2, out + 64*729);
    head_kernel<<<dim3(12, 64), 256>>>(sc, 729, w1, w2, b2, out + 64*729 + 64*625);
}

// round 7
// speedup vs baseline: 1.8728x; 1.4584x over previous
#include <cuda_runtime.h>
#include <cuda_fp16.h>
#include <math.h>

#define B 64
#define C 256

typedef unsigned long long u64;
typedef unsigned int u32;

// ---------------- f32x2 packed-math helpers ----------------
__device__ __forceinline__ u64 pack2(float lo, float hi){
    u64 r; asm("mov.b64 %0, {%1, %2};" : "=l"(r) : "f"(lo), "f"(hi)); return r;
}
__device__ __forceinline__ u64 dup2(float v){
    u64 r; asm("mov.b64 %0, {%1, %1};" : "=l"(r) : "f"(v)); return r;
}
__device__ __forceinline__ void fma2(u64 &d, u64 a, u64 b){
    asm("fma.rn.f32x2 %0, %1, %2, %0;" : "+l"(d) : "l"(a), "l"(b));
}
__device__ __forceinline__ u64 add2(u64 a, u64 b){
    u64 d; asm("add.rn.f32x2 %0, %1, %2;" : "=l"(d) : "l"(a), "l"(b)); return d;
}
__device__ __forceinline__ float2 unpk(u64 v){
    float2 f; asm("mov.b64 {%0, %1}, %2;" : "=f"(f.x), "=f"(f.y) : "l"(v)); return f;
}
// fp16 split helper: returns packed fp16x2 (hi of two values), lo likewise
__device__ __forceinline__ u32 h2pack(__half a, __half b){
    return ((u32)__half_as_ushort(b) << 16) | (u32)__half_as_ushort(a);
}

// ---------------- scratch ----------------
__device__ float g_lf[B*C*7*7];
__device__ float g_mf[B*C*5*5];
__device__ float g_sf[B*C*3*3];
__device__ float g_s [B*C*29*29];
__device__ float g_lc[B*C*27*27];
__device__ float g_mc[B*C*25*25];
__device__ float g_sc[B*C*27*27];
__device__ float g_wt[9*C*C];          // transposed search weights [khw][oc][ic], scaled x1024
__device__ float g_scale_t[C], g_bias_t[C];
__device__ float g_scale_s[C], g_bias_s[C];
__device__ float g_scale_1[C], g_bias_1[C];

// ---------------- BN folding ----------------
__global__ void prep_kernel(const float* bt,const float* gt,const float* bet,const float* mt,const float* vt,
                            const float* bs,const float* gs,const float* bes,const float* ms,const float* vs,
                            const float* b1,const float* g1,const float* be1,const float* m1,const float* v1){
    int c = threadIdx.x;
    { float inv = gt[c]*rsqrtf(vt[c]+1e-5f); g_scale_t[c]=inv; g_bias_t[c]=bt[c]*inv + bet[c] - mt[c]*inv; }
    { float inv = gs[c]*rsqrtf(vs[c]+1e-5f); g_scale_s[c]=inv; g_bias_s[c]=bs[c]*inv + bes[c] - ms[c]*inv; }
    { float inv = g1[c]*rsqrtf(v1[c]+1e-5f); g_scale_1[c]=inv; g_bias_1[c]=b1[c]*inv + be1[c] - m1[c]*inv; }
}

// ---------------- weight transpose (+ x1024 scaling for fp16-lo range) --------
__global__ void wt_trans(const float* __restrict__ w){
    int idx = blockIdx.x * 256 + threadIdx.x;
    if (idx < 9*C*C){
        int khw = idx % 9;
        int rest = idx / 9;          // oc*256 + ic
        int ic = rest & 255;
        int oc = rest >> 8;
        g_wt[khw*C*C + oc*C + ic] = w[idx] * 1024.0f;
    }
}

// ---------------- merged template conv 3x3 + BN + ReLU, f32x2 ----------------
template<int W, int NP>
__device__ __forceinline__ void row3(const float* ip, const u64* wdA, const u64* wdB,
                                     u64* aA, u64* aB){
#pragma unroll
    for (int kh = 0; kh < 3; kh++){
        float rv[2*NP+2];
#pragma unroll
        for (int j = 0; j < 2*NP+2; j++) rv[j] = ip[kh*W + j];
        u64 pe[NP+1], po[NP];
#pragma unroll
        for (int p = 0; p <= NP; p++) pe[p] = pack2(rv[2*p], rv[2*p+1]);
#pragma unroll
        for (int p = 0; p < NP; p++) po[p] = pack2(rv[2*p+1], rv[2*p+2]);
#pragma unroll
        for (int p = 0; p < NP; p++){
            fma2(aA[p], pe[p],   wdA[kh*3+0]);
            fma2(aA[p], po[p],   wdA[kh*3+1]);
            fma2(aA[p], pe[p+1], wdA[kh*3+2]);
            fma2(aB[p], pe[p],   wdB[kh*3+0]);
            fma2(aB[p], po[p],   wdB[kh*3+1]);
            fma2(aB[p], pe[p+1], wdB[kh*3+2]);
        }
    }
}

template<int OH, int NP>
__device__ __forceinline__ void tmpl_store(float* out, int b, int oc0, int row,
                                           const u64* aA, const u64* aB){
    float scA = g_scale_t[oc0],   biA = g_bias_t[oc0];
    float scB = g_scale_t[oc0+1], biB = g_bias_t[oc0+1];
    float* pA = out + (((size_t)b*C + oc0  )*OH + row)*OH;
    float* pB = out + (((size_t)b*C + oc0+1)*OH + row)*OH;
#pragma unroll
    for (int p = 0; p < NP; p++){
        float2 fa = unpk(aA[p]), fb = unpk(aB[p]);
        int col = 2*p;
        if (col < OH){
            float va = fmaf(scA, fa.x, biA); pA[col] = va > 0.f ? va : 0.f;
            float vb = fmaf(scB, fb.x, biB); pB[col] = vb > 0.f ? vb : 0.f;
        }
        if (col+1 < OH){
            float va = fmaf(scA, fa.y, biA); pA[col+1] = va > 0.f ? va : 0.f;
            float vb = fmaf(scB, fb.y, biB); pB[col+1] = vb > 0.f ? vb : 0.f;
        }
    }
}

__global__ void __launch_bounds__(512) tmpl_all(const float* __restrict__ lin,
                                                const float* __restrict__ min_,
                                                const float* __restrict__ sin_,
                                                const float* __restrict__ w,
                                                float* lo, float* mo, float* so){
    __shared__ __align__(16) float s_in[16*155 + 4];
    __shared__ __align__(16) float s_w[144*66];
    int tid = threadIdx.x;
    int ocp = tid & 31, slot = tid >> 5;
    int b = blockIdx.x, ocbase = blockIdx.y * 64;
    int oc0 = ocbase + ocp*2;

    u64 aA[4] = {0,0,0,0}, aB[4] = {0,0,0,0};

    for (int ic0 = 0; ic0 < C; ic0 += 16){
        __syncthreads();
#pragma unroll 1
        for (int idx = tid; idx < 16*155; idx += 512){
            int ic = idx / 155, r = idx % 155;
            size_t cb = (size_t)b*C + ic0 + ic;
            float v;
            if (r < 81)       v = lin [cb*81 + r];
            else if (r < 130) v = min_[cb*49 + (r-81)];
            else              v = sin_[cb*25 + (r-130)];
            s_in[ic*155 + r] = v;
        }
#pragma unroll 1
        for (int idx = tid; idx < 64*144; idx += 512){
            int oc = idx / 144, r = idx % 144;
            s_w[r*66 + oc] = w[(size_t)(ocbase+oc)*2304 + (size_t)ic0*9 + r];
        }
        __syncthreads();

        if (slot < 7){
            int row = slot;
#pragma unroll 1
            for (int ic = 0; ic < 16; ic++){
                u64 wdA[9], wdB[9];
#pragma unroll
                for (int k = 0; k < 9; k++){
                    u64 pr = *(const u64*)&s_w[(ic*9+k)*66 + ocp*2];
                    float2 f = unpk(pr);
                    wdA[k] = dup2(f.x); wdB[k] = dup2(f.y);
                }
                row3<9,4>(s_in + ic*155 + row*9, wdA, wdB, aA, aB);
            }
        } else if (slot < 12){
            int row = slot - 7;
#pragma unroll 1
            for (int ic = 0; ic < 16; ic++){
                u64 wdA[9], wdB[9];
#pragma unroll
                for (int k = 0; k < 9; k++){
                    u64 pr = *(const u64*)&s_w[(ic*9+k)*66 + ocp*2];
                    float2 f = unpk(pr);
                    wdA[k] = dup2(f.x); wdB[k] = dup2(f.y);
                }
                row3<7,3>(s_in + ic*155 + 81 + row*7, wdA, wdB, aA, aB);
            }
        } else if (slot < 15){
            int row = slot - 12;
#pragma unroll 1
            for (int ic = 0; ic < 16; ic++){
                u64 wdA[9], wdB[9];
#pragma unroll
                for (int k = 0; k < 9; k++){
                    u64 pr = *(const u64*)&s_w[(ic*9+k)*66 + ocp*2];
                    float2 f = unpk(pr);
                    wdA[k] = dup2(f.x); wdB[k] = dup2(f.y);
                }
                row3<5,2>(s_in + ic*155 + 130 + row*5, wdA, wdB, aA, aB);
            }
        }
    }

    if (slot < 7)       tmpl_store<7,4>(lo, b, oc0, slot,      aA, aB);
    else if (slot < 12) tmpl_store<5,3>(mo, b, oc0, slot - 7,  aA, aB);
    else if (slot < 15) tmpl_store<3,2>(so, b, oc0, slot - 12, aA, aB);
}

// ---------------- search conv via 3-term fp16-split mma.m16n8k16 ----------------
// grid (64 b, 7 px-tiles, 4 oc-tiles), 256 thr = 8 warps (4 M x 2 N).
// block tile: 128 px x 64 oc; warp tile 32 px x 32 oc.
// x = xh + xl (fp16); acc += Ah*Bh + Ah*Bl + Al*Bh (fp32 accum). B pre-scaled x1024.
#define SA_ROWS 248
#define SA_STRIDE 20
#define SA_N (SA_ROWS*SA_STRIDE)
#define SB_STRIDE 20
#define SB_N (64*SB_STRIDE)
#define CSM_BYTES ((2*SA_N + 2*SB_N) * 4)

#define MMA16(acc, a0,a1,a2,a3, b0,b1) \
    asm volatile( \
        "mma.sync.aligned.m16n8k16.row.col.f32.f16.f16.f32 " \
        "{%0,%1,%2,%3}, {%4,%5,%6,%7}, {%8,%9}, {%0,%1,%2,%3};" \
        : "+f"((acc)[0]), "+f"((acc)[1]), "+f"((acc)[2]), "+f"((acc)[3]) \
        : "r"(a0), "r"(a1), "r"(a2), "r"(a3), "r"(b0), "r"(b1))

__global__ void __launch_bounds__(256) conv_search_mma(const float* __restrict__ in){
    extern __shared__ u32 smem_dyn[];
    u32* sa_h = smem_dyn;
    u32* sa_l = sa_h + SA_N;
    u32* sb_h = sa_l + SA_N;
    u32* sb_l = sb_h + SB_N;

    int tid = threadIdx.x;
    int lane = tid & 31, wid = tid >> 5;
    int g = lane >> 2, t = lane & 3;
    int wm = wid & 3, wn = wid >> 2;
    int b = blockIdx.x;
    int pstart = blockIdx.y * 128;
    int ocb0 = blockIdx.z * 64;
    int r_first = pstart / 29;

    int rc0[2][2], pxv[2][2];
    bool pvalid[2][2];
#pragma unroll
    for (int mf = 0; mf < 2; mf++)
#pragma unroll
        for (int h = 0; h < 2; h++){
            int px = pstart + wm*32 + mf*16 + g + h*8;
            pvalid[mf][h] = (px < 841);
            int pxc = px < 841 ? px : 840;
            pxv[mf][h] = pxc;
            int r = pxc / 29, c = pxc - r*29;
            rc0[mf][h] = (r - r_first)*31 + c;
        }

    float acc[2][4][4];
#pragma unroll
    for (int mf = 0; mf < 2; mf++)
#pragma unroll
        for (int nf = 0; nf < 4; nf++)
#pragma unroll
            for (int i = 0; i < 4; i++) acc[mf][nf][i] = 0.f;

    const float* inb = in + (size_t)b * C * 961;

    for (int ic0 = 0; ic0 < C; ic0 += 32){
        __syncthreads();
        // stage A (hi/lo fp16x2, 16 u32 per row = 32 ic)
#pragma unroll 1
        for (int icp = 0; icp < 16; icp++){
            int rc = tid;
            if (rc < SA_ROWS){
                int gidx = r_first*31 + rc;
                int ic = ic0 + icp*2;
                float v0 = 0.f, v1 = 0.f;
                if (gidx < 961){
                    v0 = inb[ic*961 + gidx];
                    v1 = inb[(ic+1)*961 + gidx];
                }
                __half h0 = __float2half_rn(v0), h1 = __float2half_rn(v1);
                float r0 = v0 - __half2float(h0), r1 = v1 - __half2float(h1);
                sa_h[rc*SA_STRIDE + icp] = h2pack(h0, h1);
                sa_l[rc*SA_STRIDE + icp] = h2pack(__float2half_rn(r0), __float2half_rn(r1));
            }
        }
#pragma unroll 1
        for (int khw = 0; khw < 9; khw++){
            __syncthreads();
            const float* wp = g_wt + (size_t)khw*C*C + (size_t)ocb0*C + ic0;
#pragma unroll 1
            for (int idx = tid; idx < 64*16; idx += 256){
                int oc = idx >> 4, icp = idx & 15;
                float2 vv = *(const float2*)&wp[oc*C + icp*2];
                __half h0 = __float2half_rn(vv.x), h1 = __float2half_rn(vv.y);
                float r0 = vv.x - __half2float(h0), r1 = vv.y - __half2float(h1);
                sb_h[oc*SB_STRIDE + icp] = h2pack(h0, h1);
                sb_l[oc*SB_STRIDE + icp] = h2pack(__float2half_rn(r0), __float2half_rn(r1));
            }
            __syncthreads();
            int kh = khw / 3, kw = khw - kh*3;
            int sh = kh*31 + kw;
#pragma unroll
            for (int ks = 0; ks < 2; ks++){
                int k0 = ks * 8;
                u32 bh0[4], bh1[4], bl0[4], bl1[4];
#pragma unroll
                for (int nf = 0; nf < 4; nf++){
                    int ocl = wn*32 + nf*8 + g;
                    bh0[nf] = sb_h[ocl*SB_STRIDE + k0 + t];
                    bh1[nf] = sb_h[ocl*SB_STRIDE + k0 + t + 4];
                    bl0[nf] = sb_l[ocl*SB_STRIDE + k0 + t];
                    bl1[nf] = sb_l[ocl*SB_STRIDE + k0 + t + 4];
                }
#pragma unroll
                for (int mf = 0; mf < 2; mf++){
                    int i0 = (rc0[mf][0] + sh)*SA_STRIDE + k0 + t;
                    int i1 = (rc0[mf][1] + sh)*SA_STRIDE + k0 + t;
                    u32 ah0 = sa_h[i0], ah1 = sa_h[i1];
                    u32 ah2 = sa_h[i0+4], ah3 = sa_h[i1+4];
                    u32 al0 = sa_l[i0], al1 = sa_l[i1];
                    u32 al2 = sa_l[i0+4], al3 = sa_l[i1+4];
#pragma unroll
                    for (int nf = 0; nf < 4; nf++){
                        MMA16(acc[mf][nf], ah0, ah1, ah2, ah3, bh0[nf], bh1[nf]);
                        MMA16(acc[mf][nf], ah0, ah1, ah2, ah3, bl0[nf], bl1[nf]);
                        MMA16(acc[mf][nf], al0, al1, al2, al3, bh0[nf], bh1[nf]);
                    }
                }
            }
        }
    }

    // epilogue: BN + ReLU (undo x1024 weight scaling), scatter to g_s[b][oc][px]
    const float inv1024 = 0.0009765625f;
#pragma unroll
    for (int nf = 0; nf < 4; nf++){
        int oc0 = ocb0 + wn*32 + nf*8 + 2*t;
        int oc1 = oc0 + 1;
        float sc0 = g_scale_s[oc0] * inv1024, bi0 = g_bias_s[oc0];
        float sc1 = g_scale_s[oc1] * inv1024, bi1 = g_bias_s[oc1];
#pragma unroll
        for (int mf = 0; mf < 2; mf++){
            if (pvalid[mf][0]){
                float v0 = fmaf(sc0, acc[mf][nf][0], bi0);
                float v1 = fmaf(sc1, acc[mf][nf][1], bi1);
                g_s[((size_t)b*C + oc0)*841 + pxv[mf][0]] = v0 > 0.f ? v0 : 0.f;
                g_s[((size_t)b*C + oc1)*841 + pxv[mf][0]] = v1 > 0.f ? v1 : 0.f;
            }
            if (pvalid[mf][1]){
                float v2 = fmaf(sc0, acc[mf][nf][2], bi0);
                float v3 = fmaf(sc1, acc[mf][nf][3], bi1);
                g_s[((size_t)b*C + oc0)*841 + pxv[mf][1]] = v2 > 0.f ? v2 : 0.f;
                g_s[((size_t)b*C + oc1)*841 + pxv[mf][1]] = v3 > 0.f ? v3 : 0.f;
            }
        }
    }
}

// ---------------- corr v2: warp = channel, lane = output row, f32x2 --------------
template<int TS, int PAD, int OS>
__global__ void __launch_bounds__(256) corr_v2(const float* __restrict__ t,
                                               float* __restrict__ out){
    constexpr int R = OS + TS - 1;
    constexpr int STRIDE = 35;
    constexpr int NPAIR = (OS + 1) / 2;
    constexpr int VW = 2*NPAIR + TS - 1;
    constexpr int NPE = VW / 2;
    __shared__ float s_pad[8 * R * STRIDE];
    __shared__ float s_t[8 * TS * TS];
    int tid = threadIdx.x;
    int wrp = tid >> 5, lane = tid & 31;
    int b = blockIdx.x;
    int c0 = blockIdx.y * 8;

#pragma unroll 1
    for (int idx = tid; idx < 8 * R * STRIDE; idx += 256) s_pad[idx] = 0.f;
    __syncthreads();
    const float* sb = g_s + ((size_t)b*C + c0) * 841;
#pragma unroll 1
    for (int idx = tid; idx < 8 * 841; idx += 256){
        int ch = idx / 841, rem = idx - ch*841;
        int row = rem / 29, col = rem - row*29;
        s_pad[ch*R*STRIDE + (row + PAD)*STRIDE + col + PAD] = sb[ch*841 + rem];
    }
    const float* tb = t + ((size_t)b*C + c0) * TS * TS;
#pragma unroll 1
    for (int idx = tid; idx < 8 * TS * TS; idx += 256) s_t[idx] = tb[idx];
    __syncthreads();

    if (lane < OS){
        const float* sp = s_pad + wrp*R*STRIDE + lane*STRIDE;
        const float* tp = s_t + wrp*TS*TS;
        u64 a[NPAIR];
#pragma unroll
        for (int p = 0; p < NPAIR; p++) a[p] = 0ull;
#pragma unroll
        for (int trow = 0; trow < TS; trow++){
            u64 wd[TS];
#pragma unroll
            for (int j = 0; j < TS; j++) wd[j] = dup2(tp[trow*TS + j]);
            float v[VW];
#pragma unroll
            for (int k = 0; k < VW; k++) v[k] = sp[trow*STRIDE + k];
            u64 pe[NPE], po[NPE-1];
#pragma unroll
            for (int k = 0; k < NPE; k++) pe[k] = pack2(v[2*k], v[2*k+1]);
#pragma unroll
            for (int k = 0; k < NPE-1; k++) po[k] = pack2(v[2*k+1], v[2*k+2]);
#pragma unroll
            for (int j = 0; j < TS; j++){
                if (j & 1){
#pragma unroll
                    for (int p = 0; p < NPAIR; p++) fma2(a[p], po[p + (j>>1)], wd[j]);
                } else {
#pragma unroll
                    for (int p = 0; p < NPAIR; p++) fma2(a[p], pe[p + (j>>1)], wd[j]);
                }
            }
        }
        float* op = out + (((size_t)b*C + c0 + wrp)*OS + lane)*OS;
#pragma unroll
        for (int p = 0; p < NPAIR; p++){
            float2 f = unpk(a[p]);
            op[2*p] = f.x;
            if (2*p + 1 < OS) op[2*p + 1] = f.y;
        }
    }
}

// ---------------- head v2: thread = 4 n x 16 px --------------------------------
__global__ void __launch_bounds__(256) head_kernel(const float* __restrict__ x, int HW,
                                                   const float* __restrict__ w1,
                                                   const float* __restrict__ w2,
                                                   const float* __restrict__ b2,
                                                   float* __restrict__ out){
    __shared__ __align__(16) float s_w[32 * 260];
    __shared__ __align__(16) float s_x[32 * 64];
    __shared__ float s_red[8][16];
    int tid = threadIdx.x;
    int nq = tid & 63;
    int pg = tid >> 6;
    int n0 = nq * 4;
    int b = blockIdx.y;
    int p0 = blockIdx.x * 64;
    const float* xb = x + (size_t)b * C * HW;

    u64 acc[4][8];
#pragma unroll
    for (int i = 0; i < 4; i++)
#pragma unroll
        for (int p = 0; p < 8; p++) acc[i][p] = 0ull;

    for (int k0 = 0; k0 < C; k0 += 32){
        __syncthreads();
#pragma unroll 1
        for (int idx = tid; idx < 8192; idx += 256){
            int kk = idx & 31, n = idx >> 5;
            s_w[kk*260 + n] = w1[n*C + k0 + kk];
        }
#pragma unroll 1
        for (int idx = tid; idx < 2048; idx += 256){
            int p = idx & 63, kk = idx >> 6;
            int gp = p0 + p;
            s_x[kk*64 + p] = (gp < HW) ? xb[(k0+kk)*HW + gp] : 0.f;
        }
        __syncthreads();
#pragma unroll 4
        for (int kk = 0; kk < 32; kk++){
            float4 wf = *(const float4*)&s_w[kk*260 + n0];
            u64 w0 = dup2(wf.x), w1d = dup2(wf.y), w2d = dup2(wf.z), w3d = dup2(wf.w);
            const u64* xp = (const u64*)(s_x + kk*64) + pg*8;
            u64 xv[8];
#pragma unroll
            for (int p = 0; p < 8; p++) xv[p] = xp[p];
#pragma unroll
            for (int p = 0; p < 8; p++){
                fma2(acc[0][p], xv[p], w0);
                fma2(acc[1][p], xv[p], w1d);
                fma2(acc[2][p], xv[p], w2d);
                fma2(acc[3][p], xv[p], w3d);
            }
        }
    }

    u64 psum[8];
#pragma unroll
    for (int p = 0; p < 8; p++) psum[p] = 0ull;
#pragma unroll
    for (int i = 0; i < 4; i++){
        float sc = g_scale_1[n0+i], bi = g_bias_1[n0+i], wv = w2[n0+i];
#pragma unroll
        for (int p = 0; p < 8; p++){
            float2 f = unpk(acc[i][p]);
            f.x = fmaxf(fmaf(sc, f.x, bi), 0.f) * wv;
            f.y = fmaxf(fmaf(sc, f.y, bi), 0.f) * wv;
            psum[p] = add2(psum[p], pack2(f.x, f.y));
        }
    }
    int lane = tid & 31, wrp = tid >> 5;
#pragma unroll
    for (int p = 0; p < 8; p++){
        u64 v = psum[p];
        v = add2(v, __shfl_xor_sync(0xffffffffu, v, 16));
        v = add2(v, __shfl_xor_sync(0xffffffffu, v, 8));
        v = add2(v, __shfl_xor_sync(0xffffffffu, v, 4));
        v = add2(v, __shfl_xor_sync(0xffffffffu, v, 2));
        v = add2(v, __shfl_xor_sync(0xffffffffu, v, 1));
        psum[p] = v;
    }
    if (lane == 0){
#pragma unroll
        for (int p = 0; p < 8; p++){
            float2 f = unpk(psum[p]);
            s_red[wrp][2*p] = f.x;
            s_red[wrp][2*p+1] = f.y;
        }
    }
    __syncthreads();
    if (tid < 64){
        int pg2 = tid >> 4, j = tid & 15;
        float v = s_red[2*pg2][j] + s_red[2*pg2+1][j];
        int gp = p0 + pg2*16 + j;
        if (gp < HW)
            out[(size_t)b*HW + gp] = 1.f / (1.f + expf(-(v + b2[0])));
    }
}

// ---------------- launch ----------------
extern "C" void kernel_launch(void* const* d_in, const int* in_sizes, int n_in,
                              void* d_out, int out_size){
    const float* large  = (const float*)d_in[0];
    const float* medium = (const float*)d_in[1];
    const float* small  = (const float*)d_in[2];
    const float* search = (const float*)d_in[3];
    const float* wt  = (const float*)d_in[4];
    const float* bt  = (const float*)d_in[5];
    const float* gt  = (const float*)d_in[6];
    const float* bet = (const float*)d_in[7];
    const float* mt  = (const float*)d_in[8];
    const float* vt  = (const float*)d_in[9];
    const float* ws  = (const float*)d_in[10];
    const float* bs  = (const float*)d_in[11];
    const float* gs  = (const float*)d_in[12];
    const float* bes = (const float*)d_in[13];
    const float* ms  = (const float*)d_in[14];
    const float* vs  = (const float*)d_in[15];
    const float* w1  = (const float*)d_in[16];
    const float* b1  = (const float*)d_in[17];
    const float* g1  = (const float*)d_in[18];
    const float* be1 = (const float*)d_in[19];
    const float* m1  = (const float*)d_in[20];
    const float* v1  = (const float*)d_in[21];
    const float* w2  = (const float*)d_in[22];
    const float* b2  = (const float*)d_in[23];
    float* out = (float*)d_out;

    float *lf, *mf, *sf, *lc, *mc, *sc;
    cudaGetSymbolAddress((void**)&lf, g_lf);
    cudaGetSymbolAddress((void**)&mf, g_mf);
    cudaGetSymbolAddress((void**)&sf, g_sf);
    cudaGetSymbolAddress((void**)&lc, g_lc);
    cudaGetSymbolAddress((void**)&mc, g_mc);
    cudaGetSymbolAddress((void**)&sc, g_sc);

    static int smem_set = 0;
    if (!smem_set){
        cudaFuncSetAttribute(conv_search_mma,
                             cudaFuncAttributeMaxDynamicSharedMemorySize, CSM_BYTES);
        smem_set = 1;
    }

    prep_kernel<<<1, 256>>>(bt, gt, bet, mt, vt, bs, gs, bes, ms, vs, b1, g1, be1, m1, v1);
    wt_trans<<<(9*C*C + 255)/256, 256>>>(ws);

    tmpl_all<<<dim3(64, 4), 512>>>(large, medium, small, wt, lf, mf, sf);
    conv_search_mma<<<dim3(64, 7, 4), 256, CSM_BYTES>>>(search);

    corr_v2<7, 2, 27><<<dim3(64, 32), 256>>>(lf, lc);
    corr_v2<5, 0, 25><<<dim3(64, 32), 256>>>(mf, mc);
    corr_v2<3, 0, 27><<<dim3(64, 32), 256>>>(sf, sc);

    head_kernel<<<dim3(12, 64), 256>>>(lc, 729, w1, w2, b2, out);
    head_kernel<<<dim3(10, 64), 256>>>(mc, 625, w1, w2, b2, out + 64*729);
    head_kernel<<<dim3(12, 64), 256>>>(sc, 729, w1, w2, b2, out + 64*729 + 64*625);
}